// round 1
// baseline (speedup 1.0000x reference)
#include <cuda_runtime.h>
#include <cuda_bf16.h>

// Resample2d (FlowNet2 bilinear warp), fixed shapes:
//   input1 [B=4, C=64, H=384, W=512] fp32
//   input2 [B=4, 2,     H=384, W=512] fp32  (dx, dy)
//   out    [B=4, C=64, H=384, W=512] fp32
//
// Strategy: one thread per (b,h,w) pixel; compute bilinear weights + 4
// clamped gather offsets ONCE, then loop over all 64 channels. Channel
// stride is H*W so the per-channel pointer just advances by HW. Loads are
// near-coalesced across the warp (flow jitter ~N(0,1)); stores fully
// coalesced. Unroll-by-4 gives 16 independent LDGs in flight per thread.

#define RS_B 4
#define RS_C 64
#define RS_H 384
#define RS_W 512
#define RS_HW (RS_H * RS_W)          // 196608
#define RS_CHW (RS_C * RS_HW)        // 12582912

__global__ __launch_bounds__(256) void resample2d_kernel(
    const float* __restrict__ in1,   // [B,C,H,W]
    const float* __restrict__ flow,  // [B,2,H,W]
    float* __restrict__ out)         // [B,C,H,W]
{
    const int t = blockIdx.x * 256 + threadIdx.x;   // pixel index h*W+w
    const int b = blockIdx.y;
    if (t >= RS_HW) return;

    const int w = t & (RS_W - 1);
    const int h = t >> 9;                            // W = 512 = 2^9

    const float* flowb = flow + b * 2 * RS_HW;
    const float dx = flowb[t];
    const float dy = flowb[RS_HW + t];

    const float xf = (float)w + dx;
    const float yf = (float)h + dy;
    const float x0 = floorf(xf);
    const float y0 = floorf(yf);
    const float alpha = xf - x0;
    const float beta  = yf - y0;

    int x0i = (int)x0;
    int y0i = (int)y0;
    const int xL = min(max(x0i,     0), RS_W - 1);
    const int xR = min(max(x0i + 1, 0), RS_W - 1);
    const int yT = min(max(y0i,     0), RS_H - 1);
    const int yB = min(max(y0i + 1, 0), RS_H - 1);

    const float wTR = alpha * (1.0f - beta);
    const float wBL = (1.0f - alpha) * beta;
    const float wBR = alpha * beta;
    const float wTL = 1.0f - wTR - wBL - wBR;  // (1-a)(1-b), numerically fine at 1e-3 tol

    const int oTL = yT * RS_W + xL;
    const int oTR = yT * RS_W + xR;
    const int oBL = yB * RS_W + xL;
    const int oBR = yB * RS_W + xR;

    const float* base = in1 + b * RS_CHW;
    float* outp = out + b * RS_CHW + t;

#pragma unroll 4
    for (int c = 0; c < RS_C; ++c) {
        const float* p = base + c * RS_HW;
        const float vTL = __ldg(p + oTL);
        const float vTR = __ldg(p + oTR);
        const float vBL = __ldg(p + oBL);
        const float vBR = __ldg(p + oBR);
        outp[c * RS_HW] = fmaf(wTL, vTL,
                          fmaf(wTR, vTR,
                          fmaf(wBL, vBL,
                               wBR * vBR)));
    }
}

extern "C" void kernel_launch(void* const* d_in, const int* in_sizes, int n_in,
                              void* d_out, int out_size)
{
    const float* in1  = (const float*)d_in[0];
    const float* flow = (const float*)d_in[1];
    float* out = (float*)d_out;

    dim3 grid(RS_HW / 256, RS_B);   // 768 x 4 = 3072 blocks
    resample2d_kernel<<<grid, 256>>>(in1, flow, out);
}